// round 15
// baseline (speedup 1.0000x reference)
#include <cuda_runtime.h>
#include <cuda_fp16.h>
#include <math.h>
#include <math_constants.h>
#include <cstdint>

// Problem constants (Qwen3 MoE: B=1, S=1024, H=2048, E=64, I=768, top_k=8)
constexpr int T = 1024;
constexpr int H = 2048;
constexpr int E = 64;
constexpr int I = 768;
constexpr int TOPK = 8;
constexpr int NSLOT = T * TOPK;  // 8192

// ---------------- scratch (device globals) ------------------------------------
__device__ int   g_topk_idx[NSLOT];
__device__ float g_topk_w[NSLOT];
__device__ int   g_counts[E];
__device__ int   g_offsets[E + 1];
__device__ int   g_n64[E];      // number of full M64 tiles per expert
__device__ int   g_tailoff[E];  // slot offset of tail tile, or -1
__device__ int   g_tailsz[E];   // tail tile size: 0/16/32/48
__device__ int   g_fill[E];
__device__ int   g_slot_token[NSLOT];
__device__ float g_slot_w[NSLOT];
__device__ __align__(16) __half g_xh[(size_t)T * H];
__device__ __align__(16) __half g_abuf[(size_t)NSLOT * I];   // act (fp16)

// ---------------- PTX helpers -------------------------------------------------
__device__ __forceinline__ uint32_t smem_u32(const void* p) {
    uint32_t a;
    asm("{ .reg .u64 t; cvta.to.shared.u64 t, %1; cvt.u32.u64 %0, t; }" : "=r"(a) : "l"(p));
    return a;
}
__device__ __forceinline__ uint32_t h2u(__half2 h) {
    union { __half2 h; uint32_t u; } c; c.h = h; return c.u;
}
__device__ __forceinline__ void cpa16(uint32_t dst, const void* src, int sz) {
    asm volatile("cp.async.cg.shared.global [%0], [%1], 16, %2;"
                 :: "r"(dst), "l"(src), "r"(sz) : "memory");
}
#define CP_COMMIT() asm volatile("cp.async.commit_group;" ::: "memory")
#define CP_WAIT(n)  asm volatile("cp.async.wait_group %0;" :: "n"(n) : "memory")

#define LDM_X4(r0, r1, r2, r3, a) \
    asm volatile("ldmatrix.sync.aligned.m8n8.x4.shared.b16 {%0,%1,%2,%3}, [%4];" \
                 : "=r"(r0), "=r"(r1), "=r"(r2), "=r"(r3) : "r"(a))
#define LDM_X4T(r0, r1, r2, r3, a) \
    asm volatile("ldmatrix.sync.aligned.m8n8.x4.trans.shared.b16 {%0,%1,%2,%3}, [%4];" \
                 : "=r"(r0), "=r"(r1), "=r"(r2), "=r"(r3) : "r"(a))

__device__ __forceinline__ void mma16816(float& d0, float& d1, float& d2, float& d3,
                                         uint32_t a0, uint32_t a1, uint32_t a2, uint32_t a3,
                                         uint32_t b0, uint32_t b1) {
    asm volatile(
        "mma.sync.aligned.m16n8k16.row.col.f32.f16.f16.f32 "
        "{%0,%1,%2,%3}, {%4,%5,%6,%7}, {%8,%9}, {%0,%1,%2,%3};"
        : "+f"(d0), "+f"(d1), "+f"(d2), "+f"(d3)
        : "r"(a0), "r"(a1), "r"(a2), "r"(a3), "r"(b0), "r"(b1));
}

// ---------------- init --------------------------------------------------------
__global__ void init_kernel() {
    int i = threadIdx.x;
    if (i < E) { g_counts[i] = 0; g_fill[i] = 0; }
}

// ---------------- zero output --------------------------------------------------
__global__ __launch_bounds__(256) void zero_kernel(float* __restrict__ out, int n4) {
    int i = blockIdx.x * blockDim.x + threadIdx.x;
    if (i < n4) ((float4*)out)[i] = make_float4(0.f, 0.f, 0.f, 0.f);
}

// ---------------- gating: 4 tokens per block; also emits fp16 x ----------------
__global__ __launch_bounds__(256) void gate_kernel(const float* __restrict__ x,
                                                   const float* __restrict__ gw,
                                                   __half* __restrict__ xh) {
    __shared__ float xs[4][H];
    __shared__ float logits[4][E];
    const int t0 = blockIdx.x * 4;
    for (int i = threadIdx.x; i < 4 * H; i += 256)
        xs[i >> 11][i & (H - 1)] = x[(size_t)t0 * H + i];
    __syncthreads();

    // emit fp16 copy of x (from smem; no extra gmem read)
    {
        const float* xf = &xs[0][0];
        for (int i = threadIdx.x; i < 2 * H; i += 256) {
            __half2 h = __floats2half2_rn(xf[2 * i], xf[2 * i + 1]);
            *(__half2*)(xh + (size_t)t0 * H + 2 * i) = h;
        }
    }

    const int warp = threadIdx.x >> 5, lane = threadIdx.x & 31;
    for (int ee = 0; ee < 8; ee++) {
        const int e = warp * 8 + ee;
        const float* wrow = gw + (size_t)e * H;
        float a0 = 0.f, a1 = 0.f, a2 = 0.f, a3 = 0.f;
        for (int h = lane; h < H; h += 32) {
            float wv = wrow[h];
            a0 = fmaf(wv, xs[0][h], a0);
            a1 = fmaf(wv, xs[1][h], a1);
            a2 = fmaf(wv, xs[2][h], a2);
            a3 = fmaf(wv, xs[3][h], a3);
        }
        #pragma unroll
        for (int o = 16; o; o >>= 1) {
            a0 += __shfl_xor_sync(0xffffffffu, a0, o);
            a1 += __shfl_xor_sync(0xffffffffu, a1, o);
            a2 += __shfl_xor_sync(0xffffffffu, a2, o);
            a3 += __shfl_xor_sync(0xffffffffu, a3, o);
        }
        if (lane == 0) {
            logits[0][e] = a0; logits[1][e] = a1;
            logits[2][e] = a2; logits[3][e] = a3;
        }
    }
    __syncthreads();

    if (warp < 4) {
        const int t = t0 + warp;
        float l0 = logits[warp][lane], l1 = logits[warp][lane + 32];
        int sel_i[TOPK]; float sel_v[TOPK];
        #pragma unroll
        for (int k = 0; k < TOPK; k++) {
            float v; int idx;
            if (l0 >= l1) { v = l0; idx = lane; } else { v = l1; idx = lane + 32; }
            #pragma unroll
            for (int o = 16; o; o >>= 1) {
                float ov = __shfl_xor_sync(0xffffffffu, v, o);
                int   oi = __shfl_xor_sync(0xffffffffu, idx, o);
                if (ov > v || (ov == v && oi < idx)) { v = ov; idx = oi; }
            }
            sel_i[k] = idx; sel_v[k] = v;
            if (idx == lane) l0 = -CUDART_INF_F;
            else if (idx == lane + 32) l1 = -CUDART_INF_F;
        }
        if (lane == 0) {
            float m = sel_v[0];
            float ww[TOPK], s = 0.f;
            #pragma unroll
            for (int k = 0; k < TOPK; k++) { ww[k] = __expf(sel_v[k] - m); s += ww[k]; }
            float inv = 1.f / s;
            #pragma unroll
            for (int k = 0; k < TOPK; k++) {
                g_topk_idx[t * TOPK + k] = sel_i[k];
                g_topk_w[t * TOPK + k] = ww[k] * inv;
                atomicAdd(&g_counts[sel_i[k]], 1);
            }
        }
    }
}

__global__ void scan_kernel() {
    if (threadIdx.x == 0) {
        int acc = 0;
        for (int e = 0; e < E; e++) {
            g_offsets[e] = acc;
            int c = g_counts[e];
            int n64 = c >> 6, rem = c & 63;
            int ts = 0, to = -1;
            if (rem > 48) {
                n64 += 1;                       // round up to a full M64 tile
            } else if (rem > 0) {
                ts = (rem + 15) & ~15;          // 16 / 32 / 48
                to = acc + (n64 << 6);
            }
            g_n64[e] = n64;
            g_tailoff[e] = to;
            g_tailsz[e] = ts;
            acc += c;
        }
        g_offsets[E] = acc;
    }
}

__global__ void scatter_kernel() {
    int i = blockIdx.x * blockDim.x + threadIdx.x;
    if (i >= NSLOT) return;
    int t = i / TOPK;
    int e = g_topk_idx[i];
    int pos = g_offsets[e] + atomicAdd(&g_fill[e], 1);
    g_slot_token[pos] = t;
    g_slot_w[pos] = g_topk_w[i];
}

// =====================  Fused up-proj (w1 & w3 + SwiGLU)  ======================
// CTA: MT(16/32/48/64) x 128(N per mat) x 2 mats. 8 warps = 2 mat x 4 n;
// warp MT x 32. A fp16 (gathered) cp.async 3-stage. B fp32 reg-prefetched a
// FULL chunk ahead, 2-stage fp16 STS.
constexpr int UP_BROWB = 272;             // 128 halves data + 16B pad
constexpr int UP_BMATB = 32 * UP_BROWB;   // 8704
constexpr int UP_BSTGB = 2 * UP_BMATB;    // 17408
constexpr int UP_SMEM = 3 * (64 * 80) + 2 * UP_BSTGB;  // 50176

template <int MT>
__device__ __forceinline__ void up_tile(char* smem,
                                        const __half* __restrict__ X,
                                        const float* __restrict__ W1,
                                        const float* __restrict__ W3,
                                        __half* __restrict__ OUT,
                                        int e, int m0, int rend, int n0) {
    constexpr int ASTGB = MT * 80;
    constexpr int NCH = H / 32;  // 64
    const uint32_t bA = smem_u32(smem);
    const uint32_t bB = bA + 3 * ASTGB;

    const int tid = threadIdx.x, wid = tid >> 5, lane = tid & 31;
    const int gq = lane >> 2, tg = lane & 3;
    const int r8 = lane & 7, sel = lane >> 3;
    const int mat = wid >> 2, wn = wid & 3;
    const int nw = wn * 32;

    // A staging: MT rows x 4 x 16B
    const bool aact = tid < MT * 4;
    const int at = aact ? tid : 0;
    const int ar = at >> 2, aseg = at & 3;
    const int arow = m0 + ar;
    const bool aok = aact && arow < rend;
    const int asrc = aok ? g_slot_token[arow] : 0;
    const __half* aG = X + (size_t)asrc * H + aseg * 8;
    const int asz = aok ? 16 : 0;
    const uint32_t aS0 = bA + (uint32_t)(ar * 80 + aseg * 16);

    // B staging: 128 threads per mat; thread covers float offsets
    // bseg*4 + h*64 + j*16 (+0..3)  (bytes: bseg*8 + h*128 + j*32)
    const int bmat = tid >> 7;
    const int bt = tid & 127;
    const int bk = bt >> 2, bseg = bt & 3;
    const float* bGsrc = (bmat ? W3 : W1) + (size_t)e * H * I + (size_t)bk * I + n0 + bseg * 4;
    const uint32_t bS0 = bB + (uint32_t)(bmat * UP_BMATB + bk * UP_BROWB + bseg * 8);

    uint32_t aRow[MT / 16];
    #pragma unroll
    for (int mf = 0; mf < MT / 16; mf++)
        aRow[mf] = (uint32_t)((mf * 16 + ((sel & 1) << 3) + r8) * 80);
    const uint32_t aColOff = (uint32_t)(((sel >> 1) << 3) * 2);
    uint32_t bCol[2];
    #pragma unroll
    for (int nb = 0; nb < 2; nb++)
        bCol[nb] = (uint32_t)((nw + nb * 16 + ((sel >> 1) << 3)) * 2);
    const uint32_t bRowOff = (uint32_t)((((sel & 1) << 3) + r8) * UP_BROWB);
    const uint32_t bMatOff = (uint32_t)(mat * UP_BMATB);

    float4 b4[8];
    auto ldgB2 = [&](int ci) {   // both halves of next chunk
        const float* p = bGsrc + (size_t)ci * 32 * I;
        #pragma unroll
        for (int j = 0; j < 4; j++) b4[j] = *(const float4*)(p + j * 16);
        #pragma unroll
        for (int j = 0; j < 4; j++) b4[4 + j] = *(const float4*)(p + 64 + j * 16);
    };
    auto stsH = [&](int stage, int h) {
        const uint32_t d = bS0 + (uint32_t)(stage * UP_BSTGB + h * 128);
        #pragma unroll
        for (int j = 0; j < 4; j++) {
            uint32_t u0 = h2u(__floats2half2_rn(b4[4 * h + j].x, b4[4 * h + j].y));
            uint32_t u1 = h2u(__floats2half2_rn(b4[4 * h + j].z, b4[4 * h + j].w));
            asm volatile("st.shared.v2.b32 [%0], {%1,%2};"
                         :: "r"(d + j * 32), "r"(u0), "r"(u1) : "memory");
        }
    };
    auto cpaA = [&](int ci) {
        if (aact) cpa16(aS0 + (uint32_t)((ci % 3) * ASTGB), aG + ci * 32, asz);
        CP_COMMIT();
    };

    float acc[MT / 16][4][4];
    #pragma unroll
    for (int mf = 0; mf < MT / 16; mf++)
        #pragma unroll
        for (int j = 0; j < 4; j++)
            #pragma unroll
            for (int q = 0; q < 4; q++) acc[mf][j][q] = 0.f;

    ldgB2(0); stsH(0, 0); stsH(0, 1);
    cpaA(0); cpaA(1);

    for (int ci = 0; ci < NCH; ci++) {
        CP_WAIT(1);
        __syncthreads();
        if (ci + 2 < NCH) cpaA(ci + 2); else CP_COMMIT();

        const uint32_t aStg = bA + (uint32_t)((ci % 3) * ASTGB);
        const uint32_t bStg = bB + (uint32_t)((ci & 1) * UP_BSTGB) + bMatOff;
        const int nst = (ci + 1) & 1;
        const bool pf = (ci + 1 < NCH);
        if (pf) ldgB2(ci + 1);     // full-chunk LDG->STS slack

        #pragma unroll
        for (int k16 = 0; k16 < 2; k16++) {
            const uint32_t kb = k16 * 16;
            uint32_t aF[MT / 16][4], bF[2][4];
            #pragma unroll
            for (int mf = 0; mf < MT / 16; mf++)
                LDM_X4(aF[mf][0], aF[mf][1], aF[mf][2], aF[mf][3],
                       aStg + aRow[mf] + kb * 2 + aColOff);
            #pragma unroll
            for (int nb = 0; nb < 2; nb++)
                LDM_X4T(bF[nb][0], bF[nb][1], bF[nb][2], bF[nb][3],
                        bStg + kb * UP_BROWB + bRowOff + bCol[nb]);
            #pragma unroll
            for (int mf = 0; mf < MT / 16; mf++)
                #pragma unroll
                for (int j = 0; j < 4; j++)
                    mma16816(acc[mf][j][0], acc[mf][j][1], acc[mf][j][2], acc[mf][j][3],
                             aF[mf][0], aF[mf][1], aF[mf][2], aF[mf][3],
                             bF[j >> 1][(j & 1) * 2], bF[j >> 1][(j & 1) * 2 + 1]);
            if (k16 == 0 && pf) stsH(nst, 0);
        }
        if (pf) stsH(nst, 1);
    }
    __syncthreads();

    // epilogue: exchange g via smem, act = silu(g) * u
    float* exch = (float*)smem;  // MT x 132 floats
    if (mat == 0) {
        #pragma unroll
        for (int mf = 0; mf < MT / 16; mf++)
            #pragma unroll
            for (int hr = 0; hr < 2; hr++) {
                const int lr = mf * 16 + gq + hr * 8;
                #pragma unroll
                for (int j = 0; j < 4; j++) {
                    const int lc = nw + j * 8 + tg * 2;
                    exch[lr * 132 + lc] = acc[mf][j][hr * 2 + 0];
                    exch[lr * 132 + lc + 1] = acc[mf][j][hr * 2 + 1];
                }
            }
    }
    __syncthreads();
    if (mat == 1) {
        #pragma unroll
        for (int mf = 0; mf < MT / 16; mf++)
            #pragma unroll
            for (int hr = 0; hr < 2; hr++) {
                const int lr = mf * 16 + gq + hr * 8;
                const int row = m0 + lr;
                if (row >= rend) continue;
                #pragma unroll
                for (int j = 0; j < 4; j++) {
                    const int lc = nw + j * 8 + tg * 2;
                    float g0 = exch[lr * 132 + lc];
                    float g1 = exch[lr * 132 + lc + 1];
                    float u0 = acc[mf][j][hr * 2 + 0];
                    float u1 = acc[mf][j][hr * 2 + 1];
                    float v0 = u0 * g0 / (1.f + __expf(-g0));
                    float v1 = u1 * g1 / (1.f + __expf(-g1));
                    __half2* dst = (__half2*)(OUT + (size_t)row * I + n0 + lc);
                    *dst = __floats2half2_rn(v0, v1);
                }
            }
    }
}

__global__ __launch_bounds__(256, 2) void up_gemm(const __half* __restrict__ X,
                                                  const float* __restrict__ W1,
                                                  const float* __restrict__ W3,
                                                  __half* __restrict__ OUT) {
    extern __shared__ char smem[];
    const int e = blockIdx.y;
    const int n64 = g_n64[e];
    const int bx = blockIdx.x;
    const int rend = g_offsets[e + 1];
    const int n0 = blockIdx.z * 128;
    if (bx < n64) {
        up_tile<64>(smem, X, W1, W3, OUT, e, g_offsets[e] + bx * 64, rend, n0);
    } else if (bx == n64) {
        const int m0 = g_tailoff[e];
        if (m0 >= 0) {
            const int ts = g_tailsz[e];
            if (ts == 16)      up_tile<16>(smem, X, W1, W3, OUT, e, m0, rend, n0);
            else if (ts == 32) up_tile<32>(smem, X, W1, W3, OUT, e, m0, rend, n0);
            else               up_tile<48>(smem, X, W1, W3, OUT, e, m0, rend, n0);
        }
    }
}

// =====================  Down-proj (w2) + fused weighted combine  ===============
// CTA: MT x 256. 8 warps = 8 n; warp MT x 32.
// Epilogue: atomicAdd(out[token, col], w_slot * acc)  (fp32, L2-resident)
constexpr int DN_BROWB = 528;             // 256 halves data + 16B pad
constexpr int DN_BSTGB = 32 * DN_BROWB;   // 16896
constexpr int DN_SMEM = 3 * (64 * 80) + 2 * DN_BSTGB;  // 49152

template <int MT>
__device__ __forceinline__ void down_tile(char* smem,
                                          const __half* __restrict__ A,
                                          const float* __restrict__ W2,
                                          float* __restrict__ OUT,
                                          int e, int m0, int rend, int n0) {
    constexpr int ASTGB = MT * 80;
    constexpr int NCH = I / 32;  // 24
    const uint32_t bA = smem_u32(smem);
    const uint32_t bB = bA + 3 * ASTGB;

    const int tid = threadIdx.x, wid = tid >> 5, lane = tid & 31;
    const int gq = lane >> 2, tg = lane & 3;
    const int r8 = lane & 7, sel = lane >> 3;
    const int nw = wid * 32;

    const bool aact = tid < MT * 4;
    const int at = aact ? tid : 0;
    const int ar = at >> 2, aseg = at & 3;
    const int arow = m0 + ar;
    const bool aok = aact && arow < rend;
    const __half* aG = A + (size_t)(aok ? arow : 0) * I + aseg * 8;
    const int asz = aok ? 16 : 0;
    const uint32_t aS0 = bA + (uint32_t)(ar * 80 + aseg * 16);

    // B: 256 threads; thread covers float offsets bseg*4 + h*128 + j*32 (+0..3)
    // (bytes: bseg*8 + h*256 + j*64)
    const int bk = tid >> 3, bseg = tid & 7;
    const float* bGsrc = W2 + (size_t)e * I * H + (size_t)bk * H + n0 + bseg * 4;
    const uint32_t bS0 = bB + (uint32_t)(bk * DN_BROWB + bseg * 8);

    uint32_t aRow[MT / 16];
    #pragma unroll
    for (int mf = 0; mf < MT / 16; mf++)
        aRow[mf] = (uint32_t)((mf * 16 + ((sel & 1) << 3) + r8) * 80);
    const uint32_t aColOff = (uint32_t)(((sel >> 1) << 3) * 2);
    uint32_t bCol[2];
    #pragma unroll
    for (int nb = 0; nb < 2; nb++)
        bCol[nb] = (uint32_t)((nw + nb * 16 + ((sel >> 1) << 3)) * 2);
    const uint32_t bRowOff = (uint32_t)((((sel & 1) << 3) + r8) * DN_BROWB);

    float4 b4[8];
    auto ldgB2 = [&](int ci) {
        const float* p = bGsrc + (size_t)ci * 32 * H;
        #pragma unroll
        for (int j = 0; j < 4; j++) b4[j] = *(const float4*)(p + j * 32);
        #pragma unroll
        for (int j = 0; j < 4; j++) b4[4 + j] = *(const float4*)(p + 128 + j * 32);
    };
    auto stsH = [&](int stage, int h) {
        const uint32_t d = bS0 + (uint32_t)(stage * DN_BSTGB + h * 256);
        #pragma unroll
        for (int j = 0; j < 4; j++) {
            uint32_t u0 = h2u(__floats2half2_rn(b4[4 * h + j].x, b4[4 * h + j].y));
            uint32_t u1 = h2u(__floats2half2_rn(b4[4 * h + j].z, b4[4 * h + j].w));
            asm volatile("st.shared.v2.b32 [%0], {%1,%2};"
                         :: "r"(d + j * 64), "r"(u0), "r"(u1) : "memory");
        }
    };
    auto cpaA = [&](int ci) {
        if (aact) cpa16(aS0 + (uint32_t)((ci % 3) * ASTGB), aG + ci * 32, asz);
        CP_COMMIT();
    };

    float acc[MT / 16][4][4];
    #pragma unroll
    for (int mf = 0; mf < MT / 16; mf++)
        #pragma unroll
        for (int j = 0; j < 4; j++)
            #pragma unroll
            for (int q = 0; q < 4; q++) acc[mf][j][q] = 0.f;

    ldgB2(0); stsH(0, 0); stsH(0, 1);
    cpaA(0); cpaA(1);

    for (int ci = 0; ci < NCH; ci++) {
        CP_WAIT(1);
        __syncthreads();
        if (ci + 2 < NCH) cpaA(ci + 2); else CP_COMMIT();

        const uint32_t aStg = bA + (uint32_t)((ci % 3) * ASTGB);
        const uint32_t bStg = bB + (uint32_t)((ci & 1) * DN_BSTGB);
        const int nst = (ci + 1) & 1;
        const bool pf = (ci + 1 < NCH);
        if (pf) ldgB2(ci + 1);

        #pragma unroll
        for (int k16 = 0; k16 < 2; k16++) {
            const uint32_t kb = k16 * 16;
            uint32_t aF[MT / 16][4], bF[2][4];
            #pragma unroll
            for (int mf = 0; mf < MT / 16; mf++)
                LDM_X4(aF[mf][0], aF[mf][1], aF[mf][2], aF[mf][3],
                       aStg + aRow[mf] + kb * 2 + aColOff);
            #pragma unroll
            for (int nb = 0; nb < 2; nb++)
                LDM_X4T(bF[nb][0], bF[nb][1], bF[nb][2], bF[nb][3],
                        bStg + kb * DN_BROWB + bRowOff + bCol[nb]);
            #pragma unroll
            for (int mf = 0; mf < MT / 16; mf++)
                #pragma unroll
                for (int j = 0; j < 4; j++)
                    mma16816(acc[mf][j][0], acc[mf][j][1], acc[mf][j][2], acc[mf][j][3],
                             aF[mf][0], aF[mf][1], aF[mf][2], aF[mf][3],
                             bF[j >> 1][(j & 1) * 2], bF[j >> 1][(j & 1) * 2 + 1]);
            if (k16 == 0 && pf) stsH(nst, 0);
        }
        if (pf) stsH(nst, 1);
    }

    // epilogue: fused weighted combine via fp32 atomics (out is L2-resident)
    #pragma unroll
    for (int mf = 0; mf < MT / 16; mf++)
        #pragma unroll
        for (int hr = 0; hr < 2; hr++) {
            const int row = m0 + mf * 16 + gq + hr * 8;
            if (row >= rend) continue;
            const int tok = g_slot_token[row];
            const float wt = g_slot_w[row];
            float* orow = OUT + (size_t)tok * H + n0 + nw;
            #pragma unroll
            for (int j = 0; j < 4; j++) {
                const int col = j * 8 + tg * 2;
                atomicAdd(orow + col,     wt * acc[mf][j][hr * 2 + 0]);
                atomicAdd(orow + col + 1, wt * acc[mf][j][hr * 2 + 1]);
            }
        }
}

__global__ __launch_bounds__(256, 2) void down_gemm(const __half* __restrict__ A,
                                                    const float* __restrict__ W2,
                                                    float* __restrict__ OUT) {
    extern __shared__ char smem[];
    const int e = blockIdx.y;
    const int n64 = g_n64[e];
    const int bx = blockIdx.x;
    const int rend = g_offsets[e + 1];
    const int n0 = blockIdx.z * 256;
    if (bx < n64) {
        down_tile<64>(smem, A, W2, OUT, e, g_offsets[e] + bx * 64, rend, n0);
    } else if (bx == n64) {
        const int m0 = g_tailoff[e];
        if (m0 >= 0) {
            const int ts = g_tailsz[e];
            if (ts == 16)      down_tile<16>(smem, A, W2, OUT, e, m0, rend, n0);
            else if (ts == 32) down_tile<32>(smem, A, W2, OUT, e, m0, rend, n0);
            else               down_tile<48>(smem, A, W2, OUT, e, m0, rend, n0);
        }
    }
}

// ---------------- launch ------------------------------------------------------
extern "C" void kernel_launch(void* const* d_in, const int* in_sizes, int n_in,
                              void* d_out, int out_size) {
    const float* x  = (const float*)d_in[0];
    const float* gw = (const float*)d_in[1];
    const float* w1 = (const float*)d_in[2];
    const float* w3 = (const float*)d_in[3];
    const float* w2 = (const float*)d_in[4];
    float* out = (float*)d_out;

    __half *xh, *abuf;
    cudaGetSymbolAddress((void**)&xh, g_xh);
    cudaGetSymbolAddress((void**)&abuf, g_abuf);

    cudaFuncSetAttribute(up_gemm, cudaFuncAttributeMaxDynamicSharedMemorySize, UP_SMEM);
    cudaFuncSetAttribute(down_gemm, cudaFuncAttributeMaxDynamicSharedMemorySize, DN_SMEM);

    init_kernel<<<1, 64>>>();
    gate_kernel<<<T / 4, 256>>>(x, gw, xh);
    scan_kernel<<<1, 32>>>();
    scatter_kernel<<<(NSLOT + 255) / 256, 256>>>();
    zero_kernel<<<(out_size / 4 + 255) / 256, 256>>>(out, out_size / 4);

    // fused up-proj: act = silu(X@w1) * (X@w3)
    dim3 gridU(8, E, I / 128);
    up_gemm<<<gridU, 256, UP_SMEM>>>(xh, w1, w3, abuf);

    // down-proj + combine: out[token] += w_slot * (act @ w2)
    dim3 gridD(8, E, H / 256);
    down_gemm<<<gridD, 256, DN_SMEM>>>(abuf, w2, out);
}

// round 17
// speedup vs baseline: 1.0263x; 1.0263x over previous
#include <cuda_runtime.h>
#include <cuda_fp16.h>
#include <math.h>
#include <math_constants.h>
#include <cstdint>

// Problem constants (Qwen3 MoE: B=1, S=1024, H=2048, E=64, I=768, top_k=8)
constexpr int T = 1024;
constexpr int H = 2048;
constexpr int E = 64;
constexpr int I = 768;
constexpr int TOPK = 8;
constexpr int NSLOT = T * TOPK;  // 8192

// ---------------- scratch (device globals) ------------------------------------
__device__ int   g_topk_idx[NSLOT];
__device__ float g_topk_w[NSLOT];
__device__ int   g_offsets[E + 1];
__device__ int   g_n64[E];      // number of full M64 tiles per expert
__device__ int   g_tailoff[E];  // slot offset of tail tile, or -1
__device__ int   g_tailsz[E];   // tail tile size: 0/16/32/48
__device__ int   g_slot_token[NSLOT];
__device__ int   g_slot_of[NSLOT];
__device__ __align__(16) __half g_xh[(size_t)T * H];
__device__ __align__(16) __half g_abuf[(size_t)NSLOT * I];   // act (fp16)
__device__ __align__(16) __half g_ybuf[(size_t)NSLOT * H];   // y per slot (fp16)

// ---------------- PTX helpers -------------------------------------------------
__device__ __forceinline__ uint32_t smem_u32(const void* p) {
    uint32_t a;
    asm("{ .reg .u64 t; cvta.to.shared.u64 t, %1; cvt.u32.u64 %0, t; }" : "=r"(a) : "l"(p));
    return a;
}
__device__ __forceinline__ uint32_t h2u(__half2 h) {
    union { __half2 h; uint32_t u; } c; c.h = h; return c.u;
}
__device__ __forceinline__ void cpa16(uint32_t dst, const void* src, int sz) {
    asm volatile("cp.async.cg.shared.global [%0], [%1], 16, %2;"
                 :: "r"(dst), "l"(src), "r"(sz) : "memory");
}
#define CP_COMMIT() asm volatile("cp.async.commit_group;" ::: "memory")
#define CP_WAIT(n)  asm volatile("cp.async.wait_group %0;" :: "n"(n) : "memory")

#define LDM_X4(r0, r1, r2, r3, a) \
    asm volatile("ldmatrix.sync.aligned.m8n8.x4.shared.b16 {%0,%1,%2,%3}, [%4];" \
                 : "=r"(r0), "=r"(r1), "=r"(r2), "=r"(r3) : "r"(a))
#define LDM_X4T(r0, r1, r2, r3, a) \
    asm volatile("ldmatrix.sync.aligned.m8n8.x4.trans.shared.b16 {%0,%1,%2,%3}, [%4];" \
                 : "=r"(r0), "=r"(r1), "=r"(r2), "=r"(r3) : "r"(a))

__device__ __forceinline__ void mma16816(float& d0, float& d1, float& d2, float& d3,
                                         uint32_t a0, uint32_t a1, uint32_t a2, uint32_t a3,
                                         uint32_t b0, uint32_t b1) {
    asm volatile(
        "mma.sync.aligned.m16n8k16.row.col.f32.f16.f16.f32 "
        "{%0,%1,%2,%3}, {%4,%5,%6,%7}, {%8,%9}, {%0,%1,%2,%3};"
        : "+f"(d0), "+f"(d1), "+f"(d2), "+f"(d3)
        : "r"(a0), "r"(a1), "r"(a2), "r"(a3), "r"(b0), "r"(b1));
}

// ---------------- gating: 4 tokens per block; also emits fp16 x ----------------
__global__ __launch_bounds__(256) void gate_kernel(const float* __restrict__ x,
                                                   const float* __restrict__ gw,
                                                   __half* __restrict__ xh) {
    __shared__ float xs[4][H];
    __shared__ float logits[4][E];
    const int t0 = blockIdx.x * 4;
    for (int i = threadIdx.x; i < 4 * H; i += 256)
        xs[i >> 11][i & (H - 1)] = x[(size_t)t0 * H + i];
    __syncthreads();

    // emit fp16 copy of x (from smem; no extra gmem read)
    {
        const float* xf = &xs[0][0];
        for (int i = threadIdx.x; i < 2 * H; i += 256) {
            __half2 h = __floats2half2_rn(xf[2 * i], xf[2 * i + 1]);
            *(__half2*)(xh + (size_t)t0 * H + 2 * i) = h;
        }
    }

    const int warp = threadIdx.x >> 5, lane = threadIdx.x & 31;
    for (int ee = 0; ee < 8; ee++) {
        const int e = warp * 8 + ee;
        const float* wrow = gw + (size_t)e * H;
        float a0 = 0.f, a1 = 0.f, a2 = 0.f, a3 = 0.f;
        for (int h = lane; h < H; h += 32) {
            float wv = wrow[h];
            a0 = fmaf(wv, xs[0][h], a0);
            a1 = fmaf(wv, xs[1][h], a1);
            a2 = fmaf(wv, xs[2][h], a2);
            a3 = fmaf(wv, xs[3][h], a3);
        }
        #pragma unroll
        for (int o = 16; o; o >>= 1) {
            a0 += __shfl_xor_sync(0xffffffffu, a0, o);
            a1 += __shfl_xor_sync(0xffffffffu, a1, o);
            a2 += __shfl_xor_sync(0xffffffffu, a2, o);
            a3 += __shfl_xor_sync(0xffffffffu, a3, o);
        }
        if (lane == 0) {
            logits[0][e] = a0; logits[1][e] = a1;
            logits[2][e] = a2; logits[3][e] = a3;
        }
    }
    __syncthreads();

    if (warp < 4) {
        const int t = t0 + warp;
        float l0 = logits[warp][lane], l1 = logits[warp][lane + 32];
        int sel_i[TOPK]; float sel_v[TOPK];
        #pragma unroll
        for (int k = 0; k < TOPK; k++) {
            float v; int idx;
            if (l0 >= l1) { v = l0; idx = lane; } else { v = l1; idx = lane + 32; }
            #pragma unroll
            for (int o = 16; o; o >>= 1) {
                float ov = __shfl_xor_sync(0xffffffffu, v, o);
                int   oi = __shfl_xor_sync(0xffffffffu, idx, o);
                if (ov > v || (ov == v && oi < idx)) { v = ov; idx = oi; }
            }
            sel_i[k] = idx; sel_v[k] = v;
            if (idx == lane) l0 = -CUDART_INF_F;
            else if (idx == lane + 32) l1 = -CUDART_INF_F;
        }
        if (lane == 0) {
            float m = sel_v[0];
            float ww[TOPK], s = 0.f;
            #pragma unroll
            for (int k = 0; k < TOPK; k++) { ww[k] = __expf(sel_v[k] - m); s += ww[k]; }
            float inv = 1.f / s;
            #pragma unroll
            for (int k = 0; k < TOPK; k++) {
                g_topk_idx[t * TOPK + k] = sel_i[k];
                g_topk_w[t * TOPK + k] = ww[k] * inv;
            }
        }
    }
}

// ---------------- prep: histogram + scan + scatter in ONE CTA ------------------
__global__ __launch_bounds__(256) void prep_kernel() {
    __shared__ int cnt[E];
    __shared__ int off[E];
    __shared__ int fil[E];
    const int tid = threadIdx.x;
    if (tid < E) { cnt[tid] = 0; fil[tid] = 0; }
    __syncthreads();
    for (int i = tid; i < NSLOT; i += 256)
        atomicAdd(&cnt[g_topk_idx[i]], 1);
    __syncthreads();
    if (tid == 0) {
        int acc = 0;
        for (int e = 0; e < E; e++) {
            off[e] = acc;
            g_offsets[e] = acc;
            int c = cnt[e];
            int n64 = c >> 6, rem = c & 63;
            int ts = 0, to = -1;
            if (rem > 48) {
                n64 += 1;                       // round up to a full M64 tile
            } else if (rem > 0) {
                ts = (rem + 15) & ~15;          // 16 / 32 / 48
                to = acc + (n64 << 6);
            }
            g_n64[e] = n64;
            g_tailoff[e] = to;
            g_tailsz[e] = ts;
            acc += c;
        }
        g_offsets[E] = acc;
    }
    __syncthreads();
    for (int i = tid; i < NSLOT; i += 256) {
        int e = g_topk_idx[i];
        int pos = off[e] + atomicAdd(&fil[e], 1);
        g_slot_token[pos] = i / TOPK;
        g_slot_of[i] = pos;
    }
}

// =====================  Fused up-proj (w1 & w3 + SwiGLU)  ======================
// CTA: MT(16/32/48/64) x 128(N per mat) x 2 mats. 8 warps = 2 mat x 4 n;
// warp MT x 32. A fp16 (gathered) cp.async 3-stage. B fp32 reg-prefetched a
// FULL chunk ahead, 2-stage fp16 STS.
constexpr int UP_BROWB = 272;             // 128 halves data + 16B pad
constexpr int UP_BMATB = 32 * UP_BROWB;   // 8704
constexpr int UP_BSTGB = 2 * UP_BMATB;    // 17408
constexpr int UP_SMEM = 3 * (64 * 80) + 2 * UP_BSTGB;  // 50176

template <int MT>
__device__ __forceinline__ void up_tile(char* smem,
                                        const __half* __restrict__ X,
                                        const float* __restrict__ W1,
                                        const float* __restrict__ W3,
                                        __half* __restrict__ OUT,
                                        int e, int m0, int rend, int n0) {
    constexpr int ASTGB = MT * 80;
    constexpr int NCH = H / 32;  // 64
    const uint32_t bA = smem_u32(smem);
    const uint32_t bB = bA + 3 * ASTGB;

    const int tid = threadIdx.x, wid = tid >> 5, lane = tid & 31;
    const int gq = lane >> 2, tg = lane & 3;
    const int r8 = lane & 7, sel = lane >> 3;
    const int mat = wid >> 2, wn = wid & 3;
    const int nw = wn * 32;

    // A staging: MT rows x 4 x 16B
    const bool aact = tid < MT * 4;
    const int at = aact ? tid : 0;
    const int ar = at >> 2, aseg = at & 3;
    const int arow = m0 + ar;
    const bool aok = aact && arow < rend;
    const int asrc = aok ? g_slot_token[arow] : 0;
    const __half* aG = X + (size_t)asrc * H + aseg * 8;
    const int asz = aok ? 16 : 0;
    const uint32_t aS0 = bA + (uint32_t)(ar * 80 + aseg * 16);

    // B staging: 128 threads per mat; thread covers float offsets
    // bseg*4 + h*64 + j*16 (+0..3)  (bytes: bseg*8 + h*128 + j*32)
    const int bmat = tid >> 7;
    const int bt = tid & 127;
    const int bk = bt >> 2, bseg = bt & 3;
    const float* bGsrc = (bmat ? W3 : W1) + (size_t)e * H * I + (size_t)bk * I + n0 + bseg * 4;
    const uint32_t bS0 = bB + (uint32_t)(bmat * UP_BMATB + bk * UP_BROWB + bseg * 8);

    uint32_t aRow[MT / 16];
    #pragma unroll
    for (int mf = 0; mf < MT / 16; mf++)
        aRow[mf] = (uint32_t)((mf * 16 + ((sel & 1) << 3) + r8) * 80);
    const uint32_t aColOff = (uint32_t)(((sel >> 1) << 3) * 2);
    uint32_t bCol[2];
    #pragma unroll
    for (int nb = 0; nb < 2; nb++)
        bCol[nb] = (uint32_t)((nw + nb * 16 + ((sel >> 1) << 3)) * 2);
    const uint32_t bRowOff = (uint32_t)((((sel & 1) << 3) + r8) * UP_BROWB);
    const uint32_t bMatOff = (uint32_t)(mat * UP_BMATB);

    float4 b4[8];
    auto ldgB2 = [&](int ci) {   // both halves of next chunk
        const float* p = bGsrc + (size_t)ci * 32 * I;
        #pragma unroll
        for (int j = 0; j < 4; j++) b4[j] = *(const float4*)(p + j * 16);
        #pragma unroll
        for (int j = 0; j < 4; j++) b4[4 + j] = *(const float4*)(p + 64 + j * 16);
    };
    auto stsH = [&](int stage, int h) {
        const uint32_t d = bS0 + (uint32_t)(stage * UP_BSTGB + h * 128);
        #pragma unroll
        for (int j = 0; j < 4; j++) {
            uint32_t u0 = h2u(__floats2half2_rn(b4[4 * h + j].x, b4[4 * h + j].y));
            uint32_t u1 = h2u(__floats2half2_rn(b4[4 * h + j].z, b4[4 * h + j].w));
            asm volatile("st.shared.v2.b32 [%0], {%1,%2};"
                         :: "r"(d + j * 32), "r"(u0), "r"(u1) : "memory");
        }
    };
    auto cpaA = [&](int ci) {
        if (aact) cpa16(aS0 + (uint32_t)((ci % 3) * ASTGB), aG + ci * 32, asz);
        CP_COMMIT();
    };

    float acc[MT / 16][4][4];
    #pragma unroll
    for (int mf = 0; mf < MT / 16; mf++)
        #pragma unroll
        for (int j = 0; j < 4; j++)
            #pragma unroll
            for (int q = 0; q < 4; q++) acc[mf][j][q] = 0.f;

    ldgB2(0); stsH(0, 0); stsH(0, 1);
    cpaA(0); cpaA(1);

    for (int ci = 0; ci < NCH; ci++) {
        CP_WAIT(1);
        __syncthreads();
        if (ci + 2 < NCH) cpaA(ci + 2); else CP_COMMIT();

        const uint32_t aStg = bA + (uint32_t)((ci % 3) * ASTGB);
        const uint32_t bStg = bB + (uint32_t)((ci & 1) * UP_BSTGB) + bMatOff;
        const int nst = (ci + 1) & 1;
        const bool pf = (ci + 1 < NCH);
        if (pf) ldgB2(ci + 1);     // full-chunk LDG->STS slack

        #pragma unroll
        for (int k16 = 0; k16 < 2; k16++) {
            const uint32_t kb = k16 * 16;
            uint32_t aF[MT / 16][4], bF[2][4];
            #pragma unroll
            for (int mf = 0; mf < MT / 16; mf++)
                LDM_X4(aF[mf][0], aF[mf][1], aF[mf][2], aF[mf][3],
                       aStg + aRow[mf] + kb * 2 + aColOff);
            #pragma unroll
            for (int nb = 0; nb < 2; nb++)
                LDM_X4T(bF[nb][0], bF[nb][1], bF[nb][2], bF[nb][3],
                        bStg + kb * UP_BROWB + bRowOff + bCol[nb]);
            #pragma unroll
            for (int mf = 0; mf < MT / 16; mf++)
                #pragma unroll
                for (int j = 0; j < 4; j++)
                    mma16816(acc[mf][j][0], acc[mf][j][1], acc[mf][j][2], acc[mf][j][3],
                             aF[mf][0], aF[mf][1], aF[mf][2], aF[mf][3],
                             bF[j >> 1][(j & 1) * 2], bF[j >> 1][(j & 1) * 2 + 1]);
            if (k16 == 0 && pf) stsH(nst, 0);
        }
        if (pf) stsH(nst, 1);
    }
    __syncthreads();

    // epilogue: exchange g via smem, act = silu(g) * u
    float* exch = (float*)smem;  // MT x 132 floats
    if (mat == 0) {
        #pragma unroll
        for (int mf = 0; mf < MT / 16; mf++)
            #pragma unroll
            for (int hr = 0; hr < 2; hr++) {
                const int lr = mf * 16 + gq + hr * 8;
                #pragma unroll
                for (int j = 0; j < 4; j++) {
                    const int lc = nw + j * 8 + tg * 2;
                    exch[lr * 132 + lc] = acc[mf][j][hr * 2 + 0];
                    exch[lr * 132 + lc + 1] = acc[mf][j][hr * 2 + 1];
                }
            }
    }
    __syncthreads();
    if (mat == 1) {
        #pragma unroll
        for (int mf = 0; mf < MT / 16; mf++)
            #pragma unroll
            for (int hr = 0; hr < 2; hr++) {
                const int lr = mf * 16 + gq + hr * 8;
                const int row = m0 + lr;
                if (row >= rend) continue;
                #pragma unroll
                for (int j = 0; j < 4; j++) {
                    const int lc = nw + j * 8 + tg * 2;
                    float g0 = exch[lr * 132 + lc];
                    float g1 = exch[lr * 132 + lc + 1];
                    float u0 = acc[mf][j][hr * 2 + 0];
                    float u1 = acc[mf][j][hr * 2 + 1];
                    float v0 = u0 * g0 / (1.f + __expf(-g0));
                    float v1 = u1 * g1 / (1.f + __expf(-g1));
                    __half2* dst = (__half2*)(OUT + (size_t)row * I + n0 + lc);
                    *dst = __floats2half2_rn(v0, v1);
                }
            }
    }
}

__global__ __launch_bounds__(256, 2) void up_gemm(const __half* __restrict__ X,
                                                  const float* __restrict__ W1,
                                                  const float* __restrict__ W3,
                                                  __half* __restrict__ OUT) {
    extern __shared__ char smem[];
    const int e = blockIdx.y;
    const int n64 = g_n64[e];
    const int bx = blockIdx.x;
    const int rend = g_offsets[e + 1];
    const int n0 = blockIdx.z * 128;
    if (bx < n64) {
        up_tile<64>(smem, X, W1, W3, OUT, e, g_offsets[e] + bx * 64, rend, n0);
    } else if (bx == n64) {
        const int m0 = g_tailoff[e];
        if (m0 >= 0) {
            const int ts = g_tailsz[e];
            if (ts == 16)      up_tile<16>(smem, X, W1, W3, OUT, e, m0, rend, n0);
            else if (ts == 32) up_tile<32>(smem, X, W1, W3, OUT, e, m0, rend, n0);
            else               up_tile<48>(smem, X, W1, W3, OUT, e, m0, rend, n0);
        }
    }
}

// =====================  Down-proj (w2)  ========================================
// CTA: MT x 256. 8 warps = 8 n; warp MT x 32.
constexpr int DN_BROWB = 528;             // 256 halves data + 16B pad
constexpr int DN_BSTGB = 32 * DN_BROWB;   // 16896
constexpr int DN_SMEM = 3 * (64 * 80) + 2 * DN_BSTGB;  // 49152

template <int MT>
__device__ __forceinline__ void down_tile(char* smem,
                                          const __half* __restrict__ A,
                                          const float* __restrict__ W2,
                                          __half* __restrict__ OUT,
                                          int e, int m0, int rend, int n0) {
    constexpr int ASTGB = MT * 80;
    constexpr int NCH = I / 32;  // 24
    const uint32_t bA = smem_u32(smem);
    const uint32_t bB = bA + 3 * ASTGB;

    const int tid = threadIdx.x, wid = tid >> 5, lane = tid & 31;
    const int gq = lane >> 2, tg = lane & 3;
    const int r8 = lane & 7, sel = lane >> 3;
    const int nw = wid * 32;

    const bool aact = tid < MT * 4;
    const int at = aact ? tid : 0;
    const int ar = at >> 2, aseg = at & 3;
    const int arow = m0 + ar;
    const bool aok = aact && arow < rend;
    const __half* aG = A + (size_t)(aok ? arow : 0) * I + aseg * 8;
    const int asz = aok ? 16 : 0;
    const uint32_t aS0 = bA + (uint32_t)(ar * 80 + aseg * 16);

    // B: 256 threads; thread covers float offsets bseg*4 + h*128 + j*32 (+0..3)
    // (bytes: bseg*8 + h*256 + j*64)
    const int bk = tid >> 3, bseg = tid & 7;
    const float* bGsrc = W2 + (size_t)e * I * H + (size_t)bk * H + n0 + bseg * 4;
    const uint32_t bS0 = bB + (uint32_t)(bk * DN_BROWB + bseg * 8);

    uint32_t aRow[MT / 16];
    #pragma unroll
    for (int mf = 0; mf < MT / 16; mf++)
        aRow[mf] = (uint32_t)((mf * 16 + ((sel & 1) << 3) + r8) * 80);
    const uint32_t aColOff = (uint32_t)(((sel >> 1) << 3) * 2);
    uint32_t bCol[2];
    #pragma unroll
    for (int nb = 0; nb < 2; nb++)
        bCol[nb] = (uint32_t)((nw + nb * 16 + ((sel >> 1) << 3)) * 2);
    const uint32_t bRowOff = (uint32_t)((((sel & 1) << 3) + r8) * DN_BROWB);

    float4 b4[8];
    auto ldgB2 = [&](int ci) {
        const float* p = bGsrc + (size_t)ci * 32 * H;
        #pragma unroll
        for (int j = 0; j < 4; j++) b4[j] = *(const float4*)(p + j * 32);
        #pragma unroll
        for (int j = 0; j < 4; j++) b4[4 + j] = *(const float4*)(p + 128 + j * 32);
    };
    auto stsH = [&](int stage, int h) {
        const uint32_t d = bS0 + (uint32_t)(stage * DN_BSTGB + h * 256);
        #pragma unroll
        for (int j = 0; j < 4; j++) {
            uint32_t u0 = h2u(__floats2half2_rn(b4[4 * h + j].x, b4[4 * h + j].y));
            uint32_t u1 = h2u(__floats2half2_rn(b4[4 * h + j].z, b4[4 * h + j].w));
            asm volatile("st.shared.v2.b32 [%0], {%1,%2};"
                         :: "r"(d + j * 64), "r"(u0), "r"(u1) : "memory");
        }
    };
    auto cpaA = [&](int ci) {
        if (aact) cpa16(aS0 + (uint32_t)((ci % 3) * ASTGB), aG + ci * 32, asz);
        CP_COMMIT();
    };

    float acc[MT / 16][4][4];
    #pragma unroll
    for (int mf = 0; mf < MT / 16; mf++)
        #pragma unroll
        for (int j = 0; j < 4; j++)
            #pragma unroll
            for (int q = 0; q < 4; q++) acc[mf][j][q] = 0.f;

    ldgB2(0); stsH(0, 0); stsH(0, 1);
    cpaA(0); cpaA(1);

    for (int ci = 0; ci < NCH; ci++) {
        CP_WAIT(1);
        __syncthreads();
        if (ci + 2 < NCH) cpaA(ci + 2); else CP_COMMIT();

        const uint32_t aStg = bA + (uint32_t)((ci % 3) * ASTGB);
        const uint32_t bStg = bB + (uint32_t)((ci & 1) * DN_BSTGB);
        const int nst = (ci + 1) & 1;
        const bool pf = (ci + 1 < NCH);
        if (pf) ldgB2(ci + 1);

        #pragma unroll
        for (int k16 = 0; k16 < 2; k16++) {
            const uint32_t kb = k16 * 16;
            uint32_t aF[MT / 16][4], bF[2][4];
            #pragma unroll
            for (int mf = 0; mf < MT / 16; mf++)
                LDM_X4(aF[mf][0], aF[mf][1], aF[mf][2], aF[mf][3],
                       aStg + aRow[mf] + kb * 2 + aColOff);
            #pragma unroll
            for (int nb = 0; nb < 2; nb++)
                LDM_X4T(bF[nb][0], bF[nb][1], bF[nb][2], bF[nb][3],
                        bStg + kb * DN_BROWB + bRowOff + bCol[nb]);
            #pragma unroll
            for (int mf = 0; mf < MT / 16; mf++)
                #pragma unroll
                for (int j = 0; j < 4; j++)
                    mma16816(acc[mf][j][0], acc[mf][j][1], acc[mf][j][2], acc[mf][j][3],
                             aF[mf][0], aF[mf][1], aF[mf][2], aF[mf][3],
                             bF[j >> 1][(j & 1) * 2], bF[j >> 1][(j & 1) * 2 + 1]);
            if (k16 == 0 && pf) stsH(nst, 0);
        }
        if (pf) stsH(nst, 1);
    }

    #pragma unroll
    for (int mf = 0; mf < MT / 16; mf++)
        #pragma unroll
        for (int hr = 0; hr < 2; hr++) {
            const int row = m0 + mf * 16 + gq + hr * 8;
            if (row >= rend) continue;
            #pragma unroll
            for (int j = 0; j < 4; j++) {
                const int col = n0 + nw + j * 8 + tg * 2;
                __half2* dst = (__half2*)(OUT + (size_t)row * H + col);
                *dst = __floats2half2_rn(acc[mf][j][hr * 2 + 0], acc[mf][j][hr * 2 + 1]);
            }
        }
}

__global__ __launch_bounds__(256, 2) void down_gemm(const __half* __restrict__ A,
                                                    const float* __restrict__ W2,
                                                    __half* __restrict__ OUT) {
    extern __shared__ char smem[];
    const int e = blockIdx.y;
    const int n64 = g_n64[e];
    const int bx = blockIdx.x;
    const int rend = g_offsets[e + 1];
    const int n0 = blockIdx.z * 256;
    if (bx < n64) {
        down_tile<64>(smem, A, W2, OUT, e, g_offsets[e] + bx * 64, rend, n0);
    } else if (bx == n64) {
        const int m0 = g_tailoff[e];
        if (m0 >= 0) {
            const int ts = g_tailsz[e];
            if (ts == 16)      down_tile<16>(smem, A, W2, OUT, e, m0, rend, n0);
            else if (ts == 32) down_tile<32>(smem, A, W2, OUT, e, m0, rend, n0);
            else               down_tile<48>(smem, A, W2, OUT, e, m0, rend, n0);
        }
    }
}

// ---------------- combine: out[t] = sum_k w[t,k] * ybuf[slot_of[t,k]] ----------
__global__ __launch_bounds__(256) void combine_kernel(float* __restrict__ out) {
    const int t = blockIdx.x;
    __shared__ float w[TOPK];
    __shared__ int rowi[TOPK];
    if (threadIdx.x < TOPK) {
        w[threadIdx.x] = g_topk_w[t * TOPK + threadIdx.x];
        rowi[threadIdx.x] = g_slot_of[t * TOPK + threadIdx.x];
    }
    __syncthreads();
    const int j = threadIdx.x;  // 256 threads x 8 outputs = 2048 = H
    float acc[8];
    #pragma unroll
    for (int q = 0; q < 8; q++) acc[q] = 0.f;
    #pragma unroll
    for (int k = 0; k < TOPK; k++) {
        const uint4 v = *(const uint4*)(g_ybuf + (size_t)rowi[k] * H + j * 8);
        const __half2* hp = (const __half2*)&v;
        const float wk = w[k];
        #pragma unroll
        for (int q = 0; q < 4; q++) {
            float2 f = __half22float2(hp[q]);
            acc[2 * q + 0] = fmaf(wk, f.x, acc[2 * q + 0]);
            acc[2 * q + 1] = fmaf(wk, f.y, acc[2 * q + 1]);
        }
    }
    float4* orow = (float4*)(out + (size_t)t * H + j * 8);
    orow[0] = make_float4(acc[0], acc[1], acc[2], acc[3]);
    orow[1] = make_float4(acc[4], acc[5], acc[6], acc[7]);
}

// ---------------- launch ------------------------------------------------------
extern "C" void kernel_launch(void* const* d_in, const int* in_sizes, int n_in,
                              void* d_out, int out_size) {
    const float* x  = (const float*)d_in[0];
    const float* gw = (const float*)d_in[1];
    const float* w1 = (const float*)d_in[2];
    const float* w3 = (const float*)d_in[3];
    const float* w2 = (const float*)d_in[4];
    float* out = (float*)d_out;

    __half *xh, *abuf, *ybuf;
    cudaGetSymbolAddress((void**)&xh, g_xh);
    cudaGetSymbolAddress((void**)&abuf, g_abuf);
    cudaGetSymbolAddress((void**)&ybuf, g_ybuf);

    cudaFuncSetAttribute(up_gemm, cudaFuncAttributeMaxDynamicSharedMemorySize, UP_SMEM);
    cudaFuncSetAttribute(down_gemm, cudaFuncAttributeMaxDynamicSharedMemorySize, DN_SMEM);

    gate_kernel<<<T / 4, 256>>>(x, gw, xh);
    prep_kernel<<<1, 256>>>();

    // fused up-proj: act = silu(X@w1) * (X@w3)
    dim3 gridU(8, E, I / 128);
    up_gemm<<<gridU, 256, UP_SMEM>>>(xh, w1, w3, abuf);

    // down-proj: ybuf = act @ w2
    dim3 gridD(8, E, H / 256);
    down_gemm<<<gridD, 256, DN_SMEM>>>(abuf, w2, ybuf);

    combine_kernel<<<T, 256>>>(out);
}